// round 2
// baseline (speedup 1.0000x reference)
#include <cuda_runtime.h>
#include <math.h>

// ---------------- problem constants ----------------
#define NPTS   100000
#define DIN    128
#define D2     64
#define DOUT   256
#define KPTS   15
#define SIGMA  0.04f
#define NEG    0.1f
#define EPSBN  1e-5f
#define CAP    96          // max neighbors stored per query (Poisson(16) -> overflow P ~ 0)
#define QB     32          // queries per block in fused kernel

// ---------------- scratch (device globals; no runtime alloc) ----------------
__device__ float  g_t  [(size_t)NPTS * D2];     // pre-BN buffer (reused for KPConv y)
__device__ float  g_h  [(size_t)NPTS * D2];     // post BN+leaky (reused)
__device__ float  g_u2 [(size_t)NPTS * DOUT];   // ybn @ W2
__device__ float  g_usc[(size_t)NPTS * DOUT];   // x @ Wsc
__device__ int    g_cnt[NPTS];                  // edges per query
__device__ int    g_nbr[(size_t)NPTS * CAP];    // neighbor (e_ref) ids binned by query
__device__ double g_stats[1280];                // t:[0,128) y:[128,256) u2:[256,768) usc:[768,1280)

// ---------------- zero counters + stats ----------------
__global__ void zero_kernel() {
    int i = blockIdx.x * blockDim.x + threadIdx.x;
    if (i < NPTS) g_cnt[i] = 0;
    if (i < 1280) g_stats[i] = 0.0;
}

// ---------------- bin edges by query ----------------
__global__ void scatter_kernel(const int* __restrict__ e_ref,
                               const int* __restrict__ e_qry, int E) {
    int e = blockIdx.x * blockDim.x + threadIdx.x;
    if (e >= E) return;
    int q = e_qry[e];
    int r = e_ref[e];
    int slot = atomicAdd(&g_cnt[q], 1);
    if (slot < CAP) g_nbr[(size_t)q * CAP + slot] = r;
}

// ---------------- fp32 GEMM: C[M,Nc] = A[M,Kd] @ B[Kd,Nc] ----------------
// BM=128, BN=64, BK=32, 256 threads, 8x4 microtile
__global__ __launch_bounds__(256) void gemm128(
    const float* __restrict__ A, const float* __restrict__ B,
    float* __restrict__ C, int M, int Kd, int Nc)
{
    __shared__ float As[32][132];   // A^T tile
    __shared__ float Bs[32][64];

    int m0 = blockIdx.x * 128;
    int n0 = blockIdx.y * 64;
    int tid = threadIdx.x;
    int tx = tid & 15;      // col group: 4 cols
    int ty = tid >> 4;      // row group: 8 rows

    float acc[8][4];
#pragma unroll
    for (int i = 0; i < 8; ++i)
#pragma unroll
        for (int j = 0; j < 4; ++j) acc[i][j] = 0.f;

    for (int k0 = 0; k0 < Kd; k0 += 32) {
#pragma unroll
        for (int i = 0; i < 16; ++i) {        // 128x32 A tile
            int idx = tid + i * 256;
            int r = idx >> 5;
            int c = idx & 31;
            int gr = m0 + r;
            As[c][r] = (gr < M) ? A[(size_t)gr * Kd + k0 + c] : 0.f;
        }
#pragma unroll
        for (int i = 0; i < 8; ++i) {         // 32x64 B tile
            int idx = tid + i * 256;
            int r = idx >> 6;
            int c = idx & 63;
            Bs[r][c] = B[(size_t)(k0 + r) * Nc + n0 + c];
        }
        __syncthreads();
#pragma unroll
        for (int kk = 0; kk < 32; ++kk) {
            float4 a0 = *(const float4*)&As[kk][ty * 8];
            float4 a1 = *(const float4*)&As[kk][ty * 8 + 4];
            float4 b4 = *(const float4*)&Bs[kk][tx * 4];
            float av[8] = {a0.x, a0.y, a0.z, a0.w, a1.x, a1.y, a1.z, a1.w};
            float bv[4] = {b4.x, b4.y, b4.z, b4.w};
#pragma unroll
            for (int i = 0; i < 8; ++i)
#pragma unroll
                for (int j = 0; j < 4; ++j) acc[i][j] += av[i] * bv[j];
        }
        __syncthreads();
    }

#pragma unroll
    for (int i = 0; i < 8; ++i) {
        int row = m0 + ty * 8 + i;
        if (row < M) {
#pragma unroll
            for (int j = 0; j < 4; ++j)
                C[(size_t)row * Nc + n0 + tx * 4 + j] = acc[i][j];
        }
    }
}

// ---------------- per-channel sum / sumsq (fp32 inner, fp64 atomics) ----------------
template <int C>
__global__ __launch_bounds__(256) void stats_kernel(const float* __restrict__ in,
                                                    int M, int statOff) {
    const int rowsPerIter = 256 / C;
    int c  = threadIdx.x % C;
    int ro = threadIdx.x / C;
    float s = 0.f, s2 = 0.f;
    for (int r = blockIdx.x * rowsPerIter + ro; r < M; r += gridDim.x * rowsPerIter) {
        float v = in[(size_t)r * C + c];
        s += v;
        s2 += v * v;
    }
    __shared__ float sh[512];
    sh[threadIdx.x] = s;
    sh[256 + threadIdx.x] = s2;
    __syncthreads();
    if (threadIdx.x < C) {
        double ds = 0.0, ds2 = 0.0;
        for (int j = threadIdx.x; j < 256; j += C) {
            ds += (double)sh[j];
            ds2 += (double)sh[256 + j];
        }
        atomicAdd(&g_stats[statOff + c], ds);
        atomicAdd(&g_stats[statOff + C + c], ds2);
    }
}

// ---------------- BN + leaky elementwise, C=64 ----------------
__global__ void bn_apply64(const float* __restrict__ in, float* __restrict__ out,
                           int statOff,
                           const float* __restrict__ g, const float* __restrict__ b,
                           int M) {
    int i = blockIdx.x * blockDim.x + threadIdx.x;
    if (i >= M * D2) return;
    int c = i & 63;
    double m = g_stats[statOff + c] / (double)M;
    double v = g_stats[statOff + D2 + c] / (double)M - m * m;
    float rstd = rsqrtf((float)v + EPSBN);
    float scale = g[c] * rstd;
    float shift = b[c] - (float)m * scale;
    float val = in[i] * scale + shift;
    out[i] = (val >= 0.f) ? val : NEG * val;
}

// ---------------- fused KPConv: build S in smem, then S @ W_kp ----------------
// block = 32 queries, 256 threads
// smem: S_T[960][33] (127KB) + Wc[64][64] (16KB)
__global__ __launch_bounds__(256) void kpconv_fused(
    const float* __restrict__ pos, const float* __restrict__ kp,
    const float* __restrict__ Wkp,   // viewed as [960][64]
    float* __restrict__ yout)
{
    extern __shared__ float smem[];
    float* S  = smem;                 // [960][33]
    float* Wc = smem + 960 * 33;      // [64][64]

    int q0 = blockIdx.x * QB;
    int tid = threadIdx.x;
    int lane = tid & 31;
    int warp = tid >> 5;

    // zero S
    for (int i = tid; i < 960 * 33; i += 256) S[i] = 0.f;

    // cache kernel point for this lane
    float kx = 0.f, ky = 0.f, kz = 0.f;
    if (lane < KPTS) {
        kx = __ldg(&kp[lane * 3 + 0]);
        ky = __ldg(&kp[lane * 3 + 1]);
        kz = __ldg(&kp[lane * 3 + 2]);
    }
    __syncthreads();

    // -------- phase 1: accumulate S_T --------
    for (int qi = warp; qi < QB; qi += 8) {
        int q = q0 + qi;
        if (q >= NPTS) continue;
        float4 pq = __ldg((const float4*)pos + q);
        int cnt = g_cnt[q];
        if (cnt > CAP) cnt = CAP;
        const int* nb = g_nbr + (size_t)q * CAP;
        for (int j = 0; j < cnt; ++j) {
            int r = nb[j];
            float4 pr = __ldg((const float4*)pos + r);
            float rx = pr.y - pq.y;
            float ry = pr.z - pq.z;
            float rz = pr.w - pq.w;
            float infl = 0.f;
            if (lane < KPTS) {
                float dx = rx - kx, dy = ry - ky, dz = rz - kz;
                float d2 = dx * dx + dy * dy + dz * dz;
                if (d2 < SIGMA * SIGMA)
                    infl = 1.f - sqrtf(d2) * (1.f / SIGMA);
            }
            unsigned nzm = __ballot_sync(0xffffffffu, infl > 0.f);
            if (!nzm) continue;
            float h0 = __ldg(&g_h[(size_t)r * 64 + lane]);
            float h1 = __ldg(&g_h[(size_t)r * 64 + 32 + lane]);
            while (nzm) {
                int k = __ffs(nzm) - 1;
                nzm &= nzm - 1;
                float w = __shfl_sync(0xffffffffu, infl, k);
                int base = (k * 64 + lane) * 33 + qi;
                S[base]           += w * h0;
                S[base + 32 * 33] += w * h1;
            }
        }
    }
    __syncthreads();

    // -------- phase 2: y[32,64] = S_T^T @ Wkp --------
    int qg = tid & 7;          // 8 groups of 4 queries
    int cg = tid >> 3;         // 32 groups of 2 cols
    int q0t = qg * 4;
    int c0t = cg * 2;

    float acc[4][2];
#pragma unroll
    for (int i = 0; i < 4; ++i) { acc[i][0] = 0.f; acc[i][1] = 0.f; }

    for (int kc = 0; kc < KPTS; ++kc) {
        // stage W chunk (64 rows x 64 cols)
        for (int i = tid; i < 64 * 64; i += 256)
            Wc[i] = __ldg(&Wkp[(size_t)kc * 4096 + i]);
        __syncthreads();
#pragma unroll 4
        for (int kk = 0; kk < 64; ++kk) {
            int row = kc * 64 + kk;
            float sv0 = S[row * 33 + q0t + 0];
            float sv1 = S[row * 33 + q0t + 1];
            float sv2 = S[row * 33 + q0t + 2];
            float sv3 = S[row * 33 + q0t + 3];
            float wv0 = Wc[kk * 64 + c0t + 0];
            float wv1 = Wc[kk * 64 + c0t + 1];
            acc[0][0] += sv0 * wv0; acc[0][1] += sv0 * wv1;
            acc[1][0] += sv1 * wv0; acc[1][1] += sv1 * wv1;
            acc[2][0] += sv2 * wv0; acc[2][1] += sv2 * wv1;
            acc[3][0] += sv3 * wv0; acc[3][1] += sv3 * wv1;
        }
        __syncthreads();
    }

#pragma unroll
    for (int i = 0; i < 4; ++i) {
        int q = q0 + q0t + i;
        if (q < NPTS) {
            yout[(size_t)q * 64 + c0t + 0] = acc[i][0];
            yout[(size_t)q * 64 + c0t + 1] = acc[i][1];
        }
    }
}

// ---------------- final: out = leaky(bn(u2)) + bn(usc) ----------------
__global__ void final_kernel(float* __restrict__ out,
                             const float* __restrict__ g2, const float* __restrict__ b2,
                             const float* __restrict__ gsc, const float* __restrict__ bsc,
                             int M) {
    int i = blockIdx.x * blockDim.x + threadIdx.x;
    if (i >= M * DOUT) return;
    int c = i & 255;

    double m2 = g_stats[256 + c] / (double)M;
    double v2 = g_stats[256 + DOUT + c] / (double)M - m2 * m2;
    float rstd2 = rsqrtf((float)v2 + EPSBN);
    float sc2 = g2[c] * rstd2;
    float sh2 = b2[c] - (float)m2 * sc2;

    double ms = g_stats[768 + c] / (double)M;
    double vs = g_stats[768 + DOUT + c] / (double)M - ms * ms;
    float rstds = rsqrtf((float)vs + EPSBN);
    float scs = gsc[c] * rstds;
    float shs = bsc[c] - (float)ms * scs;

    float a = g_u2[i] * sc2 + sh2;
    a = (a >= 0.f) ? a : NEG * a;
    float s = g_usc[i] * scs + shs;
    out[i] = a + s;
}

// ---------------- launch ----------------
extern "C" void kernel_launch(void* const* d_in, const int* in_sizes, int n_in,
                              void* d_out, int out_size) {
    const float* pos    = (const float*)d_in[0];
    const float* x      = (const float*)d_in[1];
    const int*   e_ref  = (const int*)  d_in[2];
    const int*   e_qry  = (const int*)  d_in[3];
    const float* W1     = (const float*)d_in[4];
    const float* g1     = (const float*)d_in[5];
    const float* b1     = (const float*)d_in[6];
    const float* kp     = (const float*)d_in[7];
    const float* Wkp    = (const float*)d_in[8];
    const float* gkp    = (const float*)d_in[9];
    const float* bkp    = (const float*)d_in[10];
    const float* W2     = (const float*)d_in[11];
    const float* g2     = (const float*)d_in[12];
    const float* b2     = (const float*)d_in[13];
    const float* Wsc    = (const float*)d_in[14];
    const float* gsc    = (const float*)d_in[15];
    const float* bsc    = (const float*)d_in[16];
    float* out = (float*)d_out;

    const int M = NPTS;
    const int E = in_sizes[2];

    // resolve device-global scratch pointers
    float *t_p, *h_p, *u2_p, *usc_p;
    cudaGetSymbolAddress((void**)&t_p,   g_t);
    cudaGetSymbolAddress((void**)&h_p,   g_h);
    cudaGetSymbolAddress((void**)&u2_p,  g_u2);
    cudaGetSymbolAddress((void**)&usc_p, g_usc);

    const int FUSED_SMEM = (960 * 33 + 64 * 64) * 4;   // 143104 B
    cudaFuncSetAttribute(kpconv_fused, cudaFuncAttributeMaxDynamicSharedMemorySize, FUSED_SMEM);

    // 0. zero counters + stats
    zero_kernel<<<(NPTS + 255) / 256, 256>>>();
    // 1. bin edges by query
    scatter_kernel<<<(E + 255) / 256, 256>>>(e_ref, e_qry, E);

    dim3 grid1((M + 127) / 128, 1);
    dim3 grid4((M + 127) / 128, DOUT / 64);

    // 2. t = x @ W1
    gemm128<<<grid1, 256>>>(x, W1, t_p, M, DIN, D2);
    // 3. stats(t); h = leaky(bn(t))
    stats_kernel<64><<<592, 256>>>(t_p, M, 0);
    bn_apply64<<<(M * D2 + 255) / 256, 256>>>(t_p, h_p, 0, g1, b1, M);
    // 4. fused KPConv -> y (into g_t)
    kpconv_fused<<<(M + QB - 1) / QB, 256, FUSED_SMEM>>>(pos, kp, Wkp, t_p);
    // 5. stats(y); ybn = leaky(bn(y)) -> g_h
    stats_kernel<64><<<592, 256>>>(t_p, M, 128);
    bn_apply64<<<(M * D2 + 255) / 256, 256>>>(t_p, h_p, 128, gkp, bkp, M);
    // 6. u2 = ybn @ W2
    gemm128<<<grid4, 256>>>(h_p, W2, u2_p, M, D2, DOUT);
    // 7. usc = x @ Wsc
    gemm128<<<grid4, 256>>>(x, Wsc, usc_p, M, DIN, DOUT);
    // 8. stats for both 256-wide tensors
    stats_kernel<256><<<592, 256>>>(u2_p, M, 256);
    stats_kernel<256><<<592, 256>>>(usc_p, M, 768);
    // 9. out = leaky(bn(u2)) + bn(usc)
    final_kernel<<<(M * DOUT + 255) / 256, 256>>>(out, g2, b2, gsc, bsc, M);
}

// round 3
// speedup vs baseline: 2.0302x; 2.0302x over previous
#include <cuda_runtime.h>
#include <math.h>

// ---------------- problem constants ----------------
#define NPTS   100000
#define DIN    128
#define D2     64
#define DOUT   256
#define KPTS   15
#define SIGMA  0.04f
#define NEG    0.1f
#define EPSBN  1e-5f
#define CAP    96

// ---------------- scratch (device globals; no runtime alloc) ----------------
__device__ float  g_t  [(size_t)NPTS * D2];          // pre-BN buffer (reused for y)
__device__ float  g_h  [(size_t)NPTS * D2];          // post BN+leaky (reused for ybn)
__device__ float  g_S  [(size_t)NPTS * KPTS * D2];   // per-query aggregated features (384 MB)
__device__ float  g_u2 [(size_t)NPTS * DOUT];
__device__ float  g_usc[(size_t)NPTS * DOUT];
__device__ int    g_cnt[NPTS];
__device__ int    g_nbr[(size_t)NPTS * CAP];
__device__ double g_stats[1280];  // t:[0,128) y:[128,256) u2:[256,768) usc:[768,1280)

// ---------------- zero counters + stats ----------------
__global__ void zero_kernel() {
    int i = blockIdx.x * blockDim.x + threadIdx.x;
    if (i < NPTS) g_cnt[i] = 0;
    if (i < 1280) g_stats[i] = 0.0;
}

// ---------------- bin edges by query ----------------
__global__ void scatter_kernel(const int* __restrict__ e_ref,
                               const int* __restrict__ e_qry, int E) {
    int e = blockIdx.x * blockDim.x + threadIdx.x;
    if (e >= E) return;
    int q = e_qry[e];
    int r = e_ref[e];
    int slot = atomicAdd(&g_cnt[q], 1);
    if (slot < CAP) g_nbr[(size_t)q * CAP + slot] = r;
}

// ---------------- fp32 GEMM + fused per-column BN stats ----------------
// C[M,Nc] = A[M,Kd] @ B[Kd,Nc]; BM=128, BN=64, BK=32, 256 threads, 8x4 microtile.
// Epilogue: per-column sum/sumsq over valid rows -> fp64 atomics into g_stats.
__global__ __launch_bounds__(256) void gemm128(
    const float* __restrict__ A, const float* __restrict__ B,
    float* __restrict__ C, int M, int Kd, int Nc,
    int statOff, int statC)
{
    __shared__ float As[32][132];
    __shared__ float Bs[32][64];

    int m0 = blockIdx.x * 128;
    int n0 = blockIdx.y * 64;
    int tid = threadIdx.x;
    int tx = tid & 15;
    int ty = tid >> 4;

    float acc[8][4];
#pragma unroll
    for (int i = 0; i < 8; ++i)
#pragma unroll
        for (int j = 0; j < 4; ++j) acc[i][j] = 0.f;

    for (int k0 = 0; k0 < Kd; k0 += 32) {
#pragma unroll
        for (int i = 0; i < 16; ++i) {
            int idx = tid + i * 256;
            int r = idx >> 5;
            int c = idx & 31;
            int gr = m0 + r;
            As[c][r] = (gr < M) ? A[(size_t)gr * Kd + k0 + c] : 0.f;
        }
#pragma unroll
        for (int i = 0; i < 8; ++i) {
            int idx = tid + i * 256;
            int r = idx >> 6;
            int c = idx & 63;
            Bs[r][c] = B[(size_t)(k0 + r) * Nc + n0 + c];
        }
        __syncthreads();
#pragma unroll
        for (int kk = 0; kk < 32; ++kk) {
            float4 a0 = *(const float4*)&As[kk][ty * 8];
            float4 a1 = *(const float4*)&As[kk][ty * 8 + 4];
            float4 b4 = *(const float4*)&Bs[kk][tx * 4];
            float av[8] = {a0.x, a0.y, a0.z, a0.w, a1.x, a1.y, a1.z, a1.w};
            float bv[4] = {b4.x, b4.y, b4.z, b4.w};
#pragma unroll
            for (int i = 0; i < 8; ++i)
#pragma unroll
                for (int j = 0; j < 4; ++j) acc[i][j] += av[i] * bv[j];
        }
        __syncthreads();
    }

    // write C + thread-local column stats (valid rows only)
    float ls[4] = {0.f, 0.f, 0.f, 0.f};
    float ls2[4] = {0.f, 0.f, 0.f, 0.f};
#pragma unroll
    for (int i = 0; i < 8; ++i) {
        int row = m0 + ty * 8 + i;
        if (row < M) {
#pragma unroll
            for (int j = 0; j < 4; ++j) {
                float v = acc[i][j];
                C[(size_t)row * Nc + n0 + tx * 4 + j] = v;
                ls[j] += v;
                ls2[j] += v * v;
            }
        }
    }

    // block reduction of column stats (reuse As storage)
    float* red = &As[0][0];          // [0:64) sum, [64:128) sumsq
    if (tid < 128) red[tid] = 0.f;
    __syncthreads();
#pragma unroll
    for (int j = 0; j < 4; ++j) {
        atomicAdd(&red[tx * 4 + j], ls[j]);
        atomicAdd(&red[64 + tx * 4 + j], ls2[j]);
    }
    __syncthreads();
    if (tid < 64) {
        int ch = n0 + tid;
        atomicAdd(&g_stats[statOff + ch], (double)red[tid]);
        atomicAdd(&g_stats[statOff + statC + ch], (double)red[64 + tid]);
    }
}

// ---------------- BN + leaky elementwise, C=64 ----------------
__global__ void bn_apply64(const float* __restrict__ in, float* __restrict__ out,
                           int statOff,
                           const float* __restrict__ g, const float* __restrict__ b,
                           int M) {
    int i = blockIdx.x * blockDim.x + threadIdx.x;
    if (i >= M * D2) return;
    int c = i & 63;
    double m = g_stats[statOff + c] / (double)M;
    double v = g_stats[statOff + D2 + c] / (double)M - m * m;
    float rstd = rsqrtf((float)v + EPSBN);
    float scale = g[c] * rstd;
    float shift = b[c] - (float)m * scale;
    float val = in[i] * scale + shift;
    out[i] = (val >= 0.f) ? val : NEG * val;
}

// ---------------- S build: one warp per query, S_q in registers ----------------
__global__ __launch_bounds__(256) void sbuild_kernel(
    const float* __restrict__ pos, const float* __restrict__ kp)
{
    __shared__ float skp[45];
    int tid = threadIdx.x;
    int lane = tid & 31;
    int warp = tid >> 5;
    if (tid < 45) skp[tid] = kp[tid];
    __syncthreads();

    int q = blockIdx.x * 8 + warp;
    if (q >= NPTS) return;

    float kx = 0.f, ky = 0.f, kz = 0.f;
    if (lane < KPTS) {
        kx = skp[lane * 3 + 0];
        ky = skp[lane * 3 + 1];
        kz = skp[lane * 3 + 2];
    }

    float a0[KPTS], a1[KPTS];
#pragma unroll
    for (int k = 0; k < KPTS; ++k) { a0[k] = 0.f; a1[k] = 0.f; }

    float4 pq = __ldg((const float4*)pos + q);
    int cnt = g_cnt[q];
    if (cnt > CAP) cnt = CAP;
    const int* nb = g_nbr + (size_t)q * CAP;

    for (int j = 0; j < cnt; ++j) {
        int r = __ldg(&nb[j]);
        float4 pr = __ldg((const float4*)pos + r);
        float rx = pr.y - pq.y;
        float ry = pr.z - pq.z;
        float rz = pr.w - pq.w;
        float infl = 0.f;
        if (lane < KPTS) {
            float dx = rx - kx, dy = ry - ky, dz = rz - kz;
            float d2 = dx * dx + dy * dy + dz * dz;
            if (d2 < SIGMA * SIGMA)
                infl = 1.f - sqrtf(d2) * (1.f / SIGMA);
        }
        unsigned m = __ballot_sync(0xffffffffu, infl > 0.f);
        if (!m) continue;
        float h0 = __ldg(&g_h[(size_t)r * 64 + lane]);
        float h1 = __ldg(&g_h[(size_t)r * 64 + 32 + lane]);
#pragma unroll
        for (int k = 0; k < KPTS; ++k) {
            if (m & (1u << k)) {
                float w = __shfl_sync(0xffffffffu, infl, k);
                a0[k] += w * h0;
                a1[k] += w * h1;
            }
        }
    }

    float* Srow = g_S + (size_t)q * (KPTS * D2);
#pragma unroll
    for (int k = 0; k < KPTS; ++k) {
        Srow[k * 64 + lane]      = a0[k];
        Srow[k * 64 + 32 + lane] = a1[k];
    }
}

// ---------------- final: out = leaky(bn(u2)) + bn(usc) ----------------
__global__ void final_kernel(float* __restrict__ out,
                             const float* __restrict__ g2, const float* __restrict__ b2,
                             const float* __restrict__ gsc, const float* __restrict__ bsc,
                             int M) {
    int i = blockIdx.x * blockDim.x + threadIdx.x;
    if (i >= M * DOUT) return;
    int c = i & 255;

    double m2 = g_stats[256 + c] / (double)M;
    double v2 = g_stats[256 + DOUT + c] / (double)M - m2 * m2;
    float rstd2 = rsqrtf((float)v2 + EPSBN);
    float sc2 = g2[c] * rstd2;
    float sh2 = b2[c] - (float)m2 * sc2;

    double ms = g_stats[768 + c] / (double)M;
    double vs = g_stats[768 + DOUT + c] / (double)M - ms * ms;
    float rstds = rsqrtf((float)vs + EPSBN);
    float scs = gsc[c] * rstds;
    float shs = bsc[c] - (float)ms * scs;

    float a = g_u2[i] * sc2 + sh2;
    a = (a >= 0.f) ? a : NEG * a;
    float s = g_usc[i] * scs + shs;
    out[i] = a + s;
}

// ---------------- launch ----------------
extern "C" void kernel_launch(void* const* d_in, const int* in_sizes, int n_in,
                              void* d_out, int out_size) {
    const float* pos    = (const float*)d_in[0];
    const float* x      = (const float*)d_in[1];
    const int*   e_ref  = (const int*)  d_in[2];
    const int*   e_qry  = (const int*)  d_in[3];
    const float* W1     = (const float*)d_in[4];
    const float* g1     = (const float*)d_in[5];
    const float* b1     = (const float*)d_in[6];
    const float* kp     = (const float*)d_in[7];
    const float* Wkp    = (const float*)d_in[8];   // [15,64,64] == [960,64] row-major
    const float* gkp    = (const float*)d_in[9];
    const float* bkp    = (const float*)d_in[10];
    const float* W2     = (const float*)d_in[11];
    const float* g2     = (const float*)d_in[12];
    const float* b2     = (const float*)d_in[13];
    const float* Wsc    = (const float*)d_in[14];
    const float* gsc    = (const float*)d_in[15];
    const float* bsc    = (const float*)d_in[16];
    float* out = (float*)d_out;

    const int M = NPTS;
    const int E = in_sizes[2];

    float *t_p, *h_p, *S_p, *u2_p, *usc_p;
    cudaGetSymbolAddress((void**)&t_p,   g_t);
    cudaGetSymbolAddress((void**)&h_p,   g_h);
    cudaGetSymbolAddress((void**)&S_p,   g_S);
    cudaGetSymbolAddress((void**)&u2_p,  g_u2);
    cudaGetSymbolAddress((void**)&usc_p, g_usc);

    // 0. zero counters + stats
    zero_kernel<<<(NPTS + 255) / 256, 256>>>();
    // 1. bin edges by query
    scatter_kernel<<<(E + 255) / 256, 256>>>(e_ref, e_qry, E);

    dim3 grid1((M + 127) / 128, 1);
    dim3 grid4((M + 127) / 128, DOUT / 64);

    // 2. t = x @ W1  (+stats @0, C=64)
    gemm128<<<grid1, 256>>>(x, W1, t_p, M, DIN, D2, 0, D2);
    // 3. h = leaky(bn(t))
    bn_apply64<<<(M * D2 + 255) / 256, 256>>>(t_p, h_p, 0, g1, b1, M);
    // 4. build S (registers per warp, coalesced store, no atomics)
    sbuild_kernel<<<(M + 7) / 8, 256>>>(pos, kp);
    // 5. y = S @ Wkp  (+stats @128, C=64) -> reuse g_t
    gemm128<<<grid1, 256>>>(S_p, Wkp, t_p, M, KPTS * D2, D2, 128, D2);
    // 6. ybn = leaky(bn(y)) -> g_h
    bn_apply64<<<(M * D2 + 255) / 256, 256>>>(t_p, h_p, 128, gkp, bkp, M);
    // 7. u2 = ybn @ W2  (+stats @256, C=256)
    gemm128<<<grid4, 256>>>(h_p, W2, u2_p, M, D2, DOUT, 256, DOUT);
    // 8. usc = x @ Wsc  (+stats @768, C=256)
    gemm128<<<grid4, 256>>>(x, Wsc, usc_p, M, DIN, DOUT, 768, DOUT);
    // 9. out = leaky(bn(u2)) + bn(usc)
    final_kernel<<<(M * DOUT + 255) / 256, 256>>>(out, g2, b2, gsc, bsc, M);
}

// round 4
// speedup vs baseline: 3.9382x; 1.9398x over previous
#include <cuda_runtime.h>
#include <math.h>

// ---------------- problem constants ----------------
#define NPTS   100000
#define DIN    128
#define D2     64
#define DOUT   256
#define KPTS   15
#define SIGMA  0.04f
#define NEG    0.1f
#define EPSBN  1e-5f
#define CAP    96

// ---------------- scratch (device globals; no runtime alloc) ----------------
__device__ float  g_t  [(size_t)NPTS * D2];          // pre-BN buffer (reused for y)
__device__ float  g_h  [(size_t)NPTS * D2];          // post BN+leaky (reused for ybn)
__device__ float  g_S  [(size_t)NPTS * KPTS * D2];   // per-query aggregated features
__device__ float  g_u2 [(size_t)NPTS * DOUT];
__device__ float  g_usc[(size_t)NPTS * DOUT];
__device__ int    g_cnt[NPTS];
__device__ int    g_nbr[(size_t)NPTS * CAP];
__device__ double g_stats[1280];   // t:[0,128) y:[128,256) u2:[256,768) usc:[768,1280)
__device__ float2 g_bnp[640];      // (scale,shift): t:[0,64) y:[64,128) u2:[128,384) usc:[384,640)

// ---------------- zero counters + stats ----------------
__global__ void zero_kernel() {
    int i = blockIdx.x * blockDim.x + threadIdx.x;
    if (i < NPTS) g_cnt[i] = 0;
    if (i < 1280) g_stats[i] = 0.0;
}

// ---------------- bin edges by query ----------------
__global__ void scatter_kernel(const int* __restrict__ e_ref,
                               const int* __restrict__ e_qry, int E) {
    int e = blockIdx.x * blockDim.x + threadIdx.x;
    if (e >= E) return;
    int q = e_qry[e];
    int r = e_ref[e];
    int slot = atomicAdd(&g_cnt[q], 1);
    if (slot < CAP) g_nbr[(size_t)q * CAP + slot] = r;
}

// ---------------- per-channel BN scale/shift (fp64 done ONCE per channel) ----------------
__global__ void bn_prep(int statOff, int C, const float* __restrict__ g,
                        const float* __restrict__ b, int prepOff, int M) {
    int i = threadIdx.x;
    if (i >= C) return;
    double m = g_stats[statOff + i] / (double)M;
    double v = g_stats[statOff + C + i] / (double)M - m * m;
    float rstd = rsqrtf((float)v + EPSBN);
    float scale = g[i] * rstd;
    float shift = b[i] - (float)m * scale;
    g_bnp[prepOff + i] = make_float2(scale, shift);
}

// ---------------- fp32x2 GEMM + fused per-column BN stats ----------------
// C[M,Nc] = A[M,Kd] @ B[Kd,Nc]; BM=128, BN=64, BK=32, 256 threads.
// Microtile 8x4, accumulated as 4 row-pairs x 4 cols in packed f32x2 (FFMA2).
__global__ __launch_bounds__(256) void gemm128(
    const float* __restrict__ A, const float* __restrict__ B,
    float* __restrict__ C, int M, int Kd, int Nc,
    int statOff, int statC)
{
    __shared__ float As[32][132];      // A^T tile: As[k][row]
    __shared__ float Bs2[32][128];     // B tile with each value duplicated: (b,b) pairs

    int m0 = blockIdx.x * 128;
    int n0 = blockIdx.y * 64;
    int tid = threadIdx.x;
    int tx = tid & 15;       // 16 col groups * 4 cols
    int ty = tid >> 4;       // 16 row groups * 8 rows

    unsigned long long acc[4][4];      // [rowpair][col]
#pragma unroll
    for (int i = 0; i < 4; ++i)
#pragma unroll
        for (int j = 0; j < 4; ++j) acc[i][j] = 0ull;

    for (int k0 = 0; k0 < Kd; k0 += 32) {
#pragma unroll
        for (int i = 0; i < 16; ++i) {             // 128x32 A tile
            int idx = tid + i * 256;
            int r = idx >> 5;
            int c = idx & 31;
            int gr = m0 + r;
            As[c][r] = (gr < M) ? A[(size_t)gr * Kd + k0 + c] : 0.f;
        }
#pragma unroll
        for (int i = 0; i < 8; ++i) {              // 32x64 B tile, duplicated
            int idx = tid + i * 256;
            int r = idx >> 6;
            int c = idx & 63;
            float v = B[(size_t)(k0 + r) * Nc + n0 + c];
            float2 vv = make_float2(v, v);
            *(float2*)&Bs2[r][c * 2] = vv;
        }
        __syncthreads();
#pragma unroll
        for (int kk = 0; kk < 32; ++kk) {
            // a: 8 consecutive rows = 4 packed pairs
            ulonglong2 a01 = *(const ulonglong2*)&As[kk][ty * 8];
            ulonglong2 a23 = *(const ulonglong2*)&As[kk][ty * 8 + 4];
            // b: 4 duplicated cols = 4 packed (b,b) pairs
            ulonglong2 b01 = *(const ulonglong2*)&Bs2[kk][tx * 8];
            ulonglong2 b23 = *(const ulonglong2*)&Bs2[kk][tx * 8 + 4];
            unsigned long long ap[4] = {a01.x, a01.y, a23.x, a23.y};
            unsigned long long bp[4] = {b01.x, b01.y, b23.x, b23.y};
#pragma unroll
            for (int i = 0; i < 4; ++i)
#pragma unroll
                for (int j = 0; j < 4; ++j)
                    asm("fma.rn.f32x2 %0, %1, %2, %0;"
                        : "+l"(acc[i][j]) : "l"(ap[i]), "l"(bp[j]));
        }
        __syncthreads();
    }

    // write C + thread-local column stats
    float ls[4]  = {0.f, 0.f, 0.f, 0.f};
    float ls2[4] = {0.f, 0.f, 0.f, 0.f};
#pragma unroll
    for (int i = 0; i < 4; ++i) {
        int row0 = m0 + ty * 8 + 2 * i;
#pragma unroll
        for (int j = 0; j < 4; ++j) {
            float2 f = *(float2*)&acc[i][j];
            if (row0 < M) {
                C[(size_t)row0 * Nc + n0 + tx * 4 + j] = f.x;
                ls[j] += f.x;
                ls2[j] += f.x * f.x;
            }
            if (row0 + 1 < M) {
                C[(size_t)(row0 + 1) * Nc + n0 + tx * 4 + j] = f.y;
                ls[j] += f.y;
                ls2[j] += f.y * f.y;
            }
        }
    }

    // block reduction of column stats (reuse As storage)
    float* red = &As[0][0];            // [0:64) sum, [64:128) sumsq
    __syncthreads();
    if (tid < 128) red[tid] = 0.f;
    __syncthreads();
#pragma unroll
    for (int j = 0; j < 4; ++j) {
        atomicAdd(&red[tx * 4 + j], ls[j]);
        atomicAdd(&red[64 + tx * 4 + j], ls2[j]);
    }
    __syncthreads();
    if (tid < 64) {
        int ch = n0 + tid;
        atomicAdd(&g_stats[statOff + ch], (double)red[tid]);
        atomicAdd(&g_stats[statOff + statC + ch], (double)red[64 + tid]);
    }
}

// ---------------- BN + leaky elementwise, C=64, float4 ----------------
__global__ void bn_apply64(const float4* __restrict__ in, float4* __restrict__ out,
                           int prepOff, int n4) {
    int i = blockIdx.x * blockDim.x + threadIdx.x;
    if (i >= n4) return;
    int c4 = (i & 15) * 4;
    float2 p0 = __ldg(&g_bnp[prepOff + c4 + 0]);
    float2 p1 = __ldg(&g_bnp[prepOff + c4 + 1]);
    float2 p2 = __ldg(&g_bnp[prepOff + c4 + 2]);
    float2 p3 = __ldg(&g_bnp[prepOff + c4 + 3]);
    float4 v = in[i];
    float4 o;
    o.x = fmaf(v.x, p0.x, p0.y); o.x = (o.x >= 0.f) ? o.x : NEG * o.x;
    o.y = fmaf(v.y, p1.x, p1.y); o.y = (o.y >= 0.f) ? o.y : NEG * o.y;
    o.z = fmaf(v.z, p2.x, p2.y); o.z = (o.z >= 0.f) ? o.z : NEG * o.z;
    o.w = fmaf(v.w, p3.x, p3.y); o.w = (o.w >= 0.f) ? o.w : NEG * o.w;
    out[i] = o;
}

// ---------------- S build: one warp per query, S_q in registers ----------------
__global__ __launch_bounds__(256) void sbuild_kernel(
    const float* __restrict__ pos, const float* __restrict__ kp)
{
    __shared__ float skp[45];
    int tid = threadIdx.x;
    int lane = tid & 31;
    int warp = tid >> 5;
    if (tid < 45) skp[tid] = kp[tid];
    __syncthreads();

    int q = blockIdx.x * 8 + warp;
    if (q >= NPTS) return;

    float kx = 0.f, ky = 0.f, kz = 0.f;
    if (lane < KPTS) {
        kx = skp[lane * 3 + 0];
        ky = skp[lane * 3 + 1];
        kz = skp[lane * 3 + 2];
    }

    float a0[KPTS], a1[KPTS];
#pragma unroll
    for (int k = 0; k < KPTS; ++k) { a0[k] = 0.f; a1[k] = 0.f; }

    float4 pq = __ldg((const float4*)pos + q);
    int cnt = g_cnt[q];
    if (cnt > CAP) cnt = CAP;
    const int* nb = g_nbr + (size_t)q * CAP;

    for (int j = 0; j < cnt; ++j) {
        int r = __ldg(&nb[j]);
        float4 pr = __ldg((const float4*)pos + r);
        float rx = pr.y - pq.y;
        float ry = pr.z - pq.z;
        float rz = pr.w - pq.w;
        float infl = 0.f;
        if (lane < KPTS) {
            float dx = rx - kx, dy = ry - ky, dz = rz - kz;
            float d2 = dx * dx + dy * dy + dz * dz;
            if (d2 < SIGMA * SIGMA)
                infl = 1.f - sqrtf(d2) * (1.f / SIGMA);
        }
        unsigned m = __ballot_sync(0xffffffffu, infl > 0.f);
        if (!m) continue;
        float h0 = __ldg(&g_h[(size_t)r * 64 + lane]);
        float h1 = __ldg(&g_h[(size_t)r * 64 + 32 + lane]);
#pragma unroll
        for (int k = 0; k < KPTS; ++k) {
            if (m & (1u << k)) {
                float w = __shfl_sync(0xffffffffu, infl, k);
                a0[k] += w * h0;
                a1[k] += w * h1;
            }
        }
    }

    float* Srow = g_S + (size_t)q * (KPTS * D2);
#pragma unroll
    for (int k = 0; k < KPTS; ++k) {
        Srow[k * 64 + lane]      = a0[k];
        Srow[k * 64 + 32 + lane] = a1[k];
    }
}

// ---------------- final: out = leaky(bn(u2)) + bn(usc), float4 ----------------
__global__ void final_kernel(float4* __restrict__ out, int n4) {
    int i = blockIdx.x * blockDim.x + threadIdx.x;
    if (i >= n4) return;
    int c4 = (i & 63) * 4;
    float4 a = __ldg((const float4*)g_u2 + i);
    float4 s = __ldg((const float4*)g_usc + i);
    float4 o;
#pragma unroll
    for (int j = 0; j < 4; ++j) {
        float2 p2 = __ldg(&g_bnp[128 + c4 + j]);
        float2 ps = __ldg(&g_bnp[384 + c4 + j]);
        float av = (&a.x)[j];
        float sv = (&s.x)[j];
        float u = fmaf(av, p2.x, p2.y);
        u = (u >= 0.f) ? u : NEG * u;
        (&o.x)[j] = u + fmaf(sv, ps.x, ps.y);
    }
    out[i] = o;
}

// ---------------- launch ----------------
extern "C" void kernel_launch(void* const* d_in, const int* in_sizes, int n_in,
                              void* d_out, int out_size) {
    const float* pos    = (const float*)d_in[0];
    const float* x      = (const float*)d_in[1];
    const int*   e_ref  = (const int*)  d_in[2];
    const int*   e_qry  = (const int*)  d_in[3];
    const float* W1     = (const float*)d_in[4];
    const float* g1     = (const float*)d_in[5];
    const float* b1     = (const float*)d_in[6];
    const float* kp     = (const float*)d_in[7];
    const float* Wkp    = (const float*)d_in[8];   // [15,64,64] == [960,64] row-major
    const float* gkp    = (const float*)d_in[9];
    const float* bkp    = (const float*)d_in[10];
    const float* W2     = (const float*)d_in[11];
    const float* g2     = (const float*)d_in[12];
    const float* b2     = (const float*)d_in[13];
    const float* Wsc    = (const float*)d_in[14];
    const float* gsc    = (const float*)d_in[15];
    const float* bsc    = (const float*)d_in[16];
    float* out = (float*)d_out;

    const int M = NPTS;
    const int E = in_sizes[2];

    float *t_p, *h_p, *S_p, *u2_p, *usc_p;
    cudaGetSymbolAddress((void**)&t_p,   g_t);
    cudaGetSymbolAddress((void**)&h_p,   g_h);
    cudaGetSymbolAddress((void**)&S_p,   g_S);
    cudaGetSymbolAddress((void**)&u2_p,  g_u2);
    cudaGetSymbolAddress((void**)&usc_p, g_usc);

    // 0. zero counters + stats
    zero_kernel<<<(NPTS + 255) / 256, 256>>>();
    // 1. bin edges by query
    scatter_kernel<<<(E + 255) / 256, 256>>>(e_ref, e_qry, E);

    dim3 grid1((M + 127) / 128, 1);
    dim3 grid4((M + 127) / 128, DOUT / 64);
    int n4_64 = M * D2 / 4;
    int n4_256 = M * DOUT / 4;

    // 2. t = x @ W1  (+stats @0)
    gemm128<<<grid1, 256>>>(x, W1, t_p, M, DIN, D2, 0, D2);
    // 3. h = leaky(bn(t))
    bn_prep<<<1, 64>>>(0, D2, g1, b1, 0, M);
    bn_apply64<<<(n4_64 + 255) / 256, 256>>>((const float4*)t_p, (float4*)h_p, 0, n4_64);
    // 4. build S
    sbuild_kernel<<<(M + 7) / 8, 256>>>(pos, kp);
    // 5. y = S @ Wkp  (+stats @128) -> reuse g_t
    gemm128<<<grid1, 256>>>(S_p, Wkp, t_p, M, KPTS * D2, D2, 128, D2);
    // 6. ybn = leaky(bn(y)) -> g_h
    bn_prep<<<1, 64>>>(128, D2, gkp, bkp, 64, M);
    bn_apply64<<<(n4_64 + 255) / 256, 256>>>((const float4*)t_p, (float4*)h_p, 64, n4_64);
    // 7. u2 = ybn @ W2  (+stats @256)
    gemm128<<<grid4, 256>>>(h_p, W2, u2_p, M, D2, DOUT, 256, DOUT);
    // 8. usc = x @ Wsc  (+stats @768)
    gemm128<<<grid4, 256>>>(x, Wsc, usc_p, M, DIN, DOUT, 768, DOUT);
    // 9. prep both BN sets, then fused output
    bn_prep<<<1, 256>>>(256, DOUT, g2, b2, 128, M);
    bn_prep<<<1, 256>>>(768, DOUT, gsc, bsc, 384, M);
    final_kernel<<<(n4_256 + 255) / 256, 256>>>((float4*)out, n4_256);
}

// round 6
// speedup vs baseline: 8.6587x; 2.1986x over previous
#include <cuda_runtime.h>
#include <cuda_bf16.h>
#include <stdint.h>
#include <math.h>

// ---------------- problem constants ----------------
#define NPTS   100000
#define DIN    128
#define D2     64
#define DOUT   256
#define KPTS   15
#define SIGMA  0.04f
#define NEG    0.1f
#define EPSBN  1e-5f
#define CAP    96

// ---------------- scratch (device globals; no runtime alloc) ----------------
__device__ float  g_t  [(size_t)NPTS * D2];      // fp32 GEMM out (t, then y)
__device__ float  g_h  [(size_t)NPTS * D2];      // post BN+leaky fp32 (feeds sbuild)
__device__ float  g_u2 [(size_t)NPTS * DOUT];
__device__ float  g_usc[(size_t)NPTS * DOUT];
__device__ __align__(16) __nv_bfloat16 g_xb [(size_t)NPTS * 2 * DIN];        // x split: [hi|lo]
__device__ __align__(16) __nv_bfloat16 g_yb [(size_t)NPTS * 2 * D2];         // ybn split
__device__ __align__(16) __nv_bfloat16 g_Sb [(size_t)NPTS * 2 * KPTS * D2];  // S split
__device__ __align__(16) __nv_bfloat16 g_w1b [D2   * 2 * DIN];   // Bt[n][2K]
__device__ __align__(16) __nv_bfloat16 g_wkpb[D2   * 2 * (KPTS*D2)];
__device__ __align__(16) __nv_bfloat16 g_w2b [DOUT * 2 * D2];
__device__ __align__(16) __nv_bfloat16 g_wscb[DOUT * 2 * DIN];
__device__ int    g_cnt[NPTS];
__device__ int    g_nbr[(size_t)NPTS * CAP];
__device__ double g_stats[1280];   // t:[0,128) y:[128,256) u2:[256,768) usc:[768,1280)
__device__ float2 g_bnp[640];      // (scale,shift): t:[0,64) y:[64,128) u2:[128,384) usc:[384,640)

// ---------------- small kernels ----------------
__global__ void zero_kernel() {
    int i = blockIdx.x * blockDim.x + threadIdx.x;
    if (i < NPTS) g_cnt[i] = 0;
    if (i < 1280) g_stats[i] = 0.0;
}

__global__ void scatter_kernel(const int* __restrict__ e_ref,
                               const int* __restrict__ e_qry, int E) {
    int e = blockIdx.x * blockDim.x + threadIdx.x;
    if (e >= E) return;
    int q = e_qry[e];
    int r = e_ref[e];
    int slot = atomicAdd(&g_cnt[q], 1);
    if (slot < CAP) g_nbr[(size_t)q * CAP + slot] = r;
}

__device__ __forceinline__ void bsplit(float v, __nv_bfloat16& h, __nv_bfloat16& l) {
    h = __float2bfloat16(v);
    l = __float2bfloat16(v - __bfloat162float(h));
}

__global__ void xsplit_kernel(const float* __restrict__ x, int n) {
    int i = blockIdx.x * blockDim.x + threadIdx.x;
    if (i >= n) return;
    int q = i / DIN, c = i % DIN;
    __nv_bfloat16 h, l;
    bsplit(x[i], h, l);
    g_xb[(size_t)q * 2 * DIN + c] = h;
    g_xb[(size_t)q * 2 * DIN + DIN + c] = l;
}

// W [K, N] fp32 -> out [N, 2K] bf16 (hi | lo)
__global__ void wsplit_kernel(const float* __restrict__ W, __nv_bfloat16* __restrict__ out,
                              int K, int N) {
    int i = blockIdx.x * blockDim.x + threadIdx.x;
    if (i >= K * N) return;
    int k = i / N, n = i % N;
    __nv_bfloat16 h, l;
    bsplit(W[i], h, l);
    out[(size_t)n * 2 * K + k] = h;
    out[(size_t)n * 2 * K + K + k] = l;
}

__global__ void bn_prep(int statOff, int C, const float* __restrict__ g,
                        const float* __restrict__ b, int prepOff, int M) {
    int i = threadIdx.x;
    if (i >= C) return;
    double m = g_stats[statOff + i] / (double)M;
    double v = g_stats[statOff + C + i] / (double)M - m * m;
    float rstd = rsqrtf((float)v + EPSBN);
    float scale = g[i] * rstd;
    float shift = b[i] - (float)m * scale;
    g_bnp[prepOff + i] = make_float2(scale, shift);
}

__global__ void bn_apply64(const float4* __restrict__ in, float4* __restrict__ out,
                           int prepOff, int n4) {
    int i = blockIdx.x * blockDim.x + threadIdx.x;
    if (i >= n4) return;
    int c4 = (i & 15) * 4;
    float4 v = in[i];
    float4 o;
#pragma unroll
    for (int j = 0; j < 4; ++j) {
        float2 p = __ldg(&g_bnp[prepOff + c4 + j]);
        float u = fmaf((&v.x)[j], p.x, p.y);
        (&o.x)[j] = (u >= 0.f) ? u : NEG * u;
    }
    out[i] = o;
}

// BN + leaky, split bf16 out (feeds u2 GEMM), C=64
__global__ void bn_apply_ysplit(const float* __restrict__ in, int prepOff, int n) {
    int i = blockIdx.x * blockDim.x + threadIdx.x;
    if (i >= n) return;
    int c = i & 63, q = i >> 6;
    float2 p = __ldg(&g_bnp[prepOff + c]);
    float u = fmaf(in[i], p.x, p.y);
    u = (u >= 0.f) ? u : NEG * u;
    __nv_bfloat16 h, l;
    bsplit(u, h, l);
    g_yb[(size_t)q * 128 + c] = h;
    g_yb[(size_t)q * 128 + 64 + c] = l;
}

// ---------------- S build: one warp per query, split bf16 out ----------------
__global__ __launch_bounds__(256) void sbuild_kernel(
    const float* __restrict__ pos, const float* __restrict__ kp)
{
    __shared__ float skp[45];
    int tid = threadIdx.x;
    int lane = tid & 31;
    int warp = tid >> 5;
    if (tid < 45) skp[tid] = kp[tid];
    __syncthreads();

    int q = blockIdx.x * 8 + warp;
    if (q >= NPTS) return;

    float kx = 0.f, ky = 0.f, kz = 0.f;
    if (lane < KPTS) {
        kx = skp[lane * 3 + 0];
        ky = skp[lane * 3 + 1];
        kz = skp[lane * 3 + 2];
    }

    float a0[KPTS], a1[KPTS];
#pragma unroll
    for (int k = 0; k < KPTS; ++k) { a0[k] = 0.f; a1[k] = 0.f; }

    float4 pq = __ldg((const float4*)pos + q);
    int cnt = g_cnt[q];
    if (cnt > CAP) cnt = CAP;
    const int* nb = g_nbr + (size_t)q * CAP;

    for (int j = 0; j < cnt; ++j) {
        int r = __ldg(&nb[j]);
        float4 pr = __ldg((const float4*)pos + r);
        float rx = pr.y - pq.y;
        float ry = pr.z - pq.z;
        float rz = pr.w - pq.w;
        float infl = 0.f;
        if (lane < KPTS) {
            float dx = rx - kx, dy = ry - ky, dz = rz - kz;
            float d2 = dx * dx + dy * dy + dz * dz;
            if (d2 < SIGMA * SIGMA)
                infl = 1.f - sqrtf(d2) * (1.f / SIGMA);
        }
        unsigned m = __ballot_sync(0xffffffffu, infl > 0.f);
        if (!m) continue;
        float2 hv = __ldg((const float2*)g_h + (size_t)r * 32 + lane);
#pragma unroll
        for (int k = 0; k < KPTS; ++k) {
            if (m & (1u << k)) {
                float w = __shfl_sync(0xffffffffu, infl, k);
                a0[k] += w * hv.x;
                a1[k] += w * hv.y;
            }
        }
    }

    // split bf16: hi elems [0,960), lo [960,1920); lane owns channels 2lane,2lane+1
    __nv_bfloat162* Sout = (__nv_bfloat162*)(g_Sb + (size_t)q * 1920);
#pragma unroll
    for (int k = 0; k < KPTS; ++k) {
        __nv_bfloat16 h0, l0, h1, l1;
        bsplit(a0[k], h0, l0);
        bsplit(a1[k], h1, l1);
        __nv_bfloat162 hh; hh.x = h0; hh.y = h1;
        __nv_bfloat162 ll; ll.x = l0; ll.y = l1;
        Sout[k * 32 + lane] = hh;
        Sout[480 + k * 32 + lane] = ll;
    }
}

// ---------------- warp-MMA GEMM: C[M,Nc] = A @ B^T (split bf16, 3-term) ----------------
// A: [M, 2K] bf16 (hi|lo per row), B: [Nc, 2K] bf16 (hi|lo per row), C fp32.
// CTA tile 128x64, 8 warps of 32x32, BK=64 chunks, mma.sync m16n8k16 bf16.
// Epilogue: direct C writes + fused per-column BN stats.
#define ROWP 72                       // padded smem row (bf16 elems)
#define A_SEC (128 * ROWP)
#define B_SEC (64 * ROWP)
#define GSMEM_BYTES ((2 * A_SEC + 2 * B_SEC) * 2 + 512)

__device__ __forceinline__ void mma16816(float* c, const uint32_t* a, const uint32_t* b) {
    asm volatile(
        "mma.sync.aligned.m16n8k16.row.col.f32.bf16.bf16.f32 "
        "{%0,%1,%2,%3}, {%4,%5,%6,%7}, {%8,%9}, {%0,%1,%2,%3};"
        : "+f"(c[0]), "+f"(c[1]), "+f"(c[2]), "+f"(c[3])
        : "r"(a[0]), "r"(a[1]), "r"(a[2]), "r"(a[3]), "r"(b[0]), "r"(b[1]));
}

__global__ __launch_bounds__(256) void gemm_mma(
    const __nv_bfloat16* __restrict__ A,
    const __nv_bfloat16* __restrict__ B,
    float* __restrict__ C,
    int M, int K, int Nc, int statOff, int statC)
{
    extern __shared__ char smem[];
    __nv_bfloat16* sA = (__nv_bfloat16*)smem;                 // hi [128][72], lo follows
    __nv_bfloat16* sB = sA + 2 * A_SEC;                       // hi [64][72], lo follows
    float* red = (float*)(smem + (2 * A_SEC + 2 * B_SEC) * 2);

    const int tid = threadIdx.x;
    const int lane = tid & 31;
    const int wid = tid >> 5;
    const int wm = wid & 3;            // 4 m-blocks of 32
    const int wn = wid >> 2;           // 2 n-blocks of 32
    const int g = lane >> 2;
    const int t = lane & 3;
    const int m0 = blockIdx.x * 128;
    const int n0 = blockIdx.y * 64;
    const int lda = 2 * K;
    const int nch = K >> 6;

    if (tid < 128) red[tid] = 0.f;

    float acc[2][4][4];
#pragma unroll
    for (int mi = 0; mi < 2; ++mi)
#pragma unroll
        for (int ni = 0; ni < 4; ++ni)
#pragma unroll
            for (int j = 0; j < 4; ++j) acc[mi][ni][j] = 0.f;

    for (int c = 0; c < nch; ++c) {
        int koh = c * 64;
        // stage A (128x64 hi + lo)
#pragma unroll
        for (int i = 0; i < 4; ++i) {
            int idx = tid + 256 * i;
            int r = idx >> 3, cw = idx & 7;
            int gr = m0 + r;
            uint4 vh = make_uint4(0, 0, 0, 0), vl = vh;
            if (gr < M) {
                const uint4* base = (const uint4*)(A + (size_t)gr * lda);
                vh = __ldg(base + (koh >> 3) + cw);
                vl = __ldg(base + ((K + koh) >> 3) + cw);
            }
            *(uint4*)(sA + r * ROWP + cw * 8) = vh;
            *(uint4*)(sA + A_SEC + r * ROWP + cw * 8) = vl;
        }
        // stage B (64x64 hi + lo)
#pragma unroll
        for (int i = 0; i < 2; ++i) {
            int idx = tid + 256 * i;
            int r = idx >> 3, cw = idx & 7;
            const uint4* base = (const uint4*)(B + (size_t)(n0 + r) * lda);
            uint4 vh = __ldg(base + (koh >> 3) + cw);
            uint4 vl = __ldg(base + ((K + koh) >> 3) + cw);
            *(uint4*)(sB + r * ROWP + cw * 8) = vh;
            *(uint4*)(sB + B_SEC + r * ROWP + cw * 8) = vl;
        }
        __syncthreads();

#pragma unroll
        for (int ks = 0; ks < 4; ++ks) {
            int col = ks * 16 + 2 * t;
            uint32_t ah[2][4], al[2][4];
#pragma unroll
            for (int mi = 0; mi < 2; ++mi) {
                const __nv_bfloat16* p = sA + (wm * 32 + mi * 16 + g) * ROWP + col;
                ah[mi][0] = *(const uint32_t*)p;
                ah[mi][1] = *(const uint32_t*)(p + 8 * ROWP);
                ah[mi][2] = *(const uint32_t*)(p + 8);
                ah[mi][3] = *(const uint32_t*)(p + 8 * ROWP + 8);
                const __nv_bfloat16* q = p + A_SEC;
                al[mi][0] = *(const uint32_t*)q;
                al[mi][1] = *(const uint32_t*)(q + 8 * ROWP);
                al[mi][2] = *(const uint32_t*)(q + 8);
                al[mi][3] = *(const uint32_t*)(q + 8 * ROWP + 8);
            }
            uint32_t bh[4][2], bl[4][2];
#pragma unroll
            for (int ni = 0; ni < 4; ++ni) {
                const __nv_bfloat16* p = sB + (wn * 32 + ni * 8 + g) * ROWP + col;
                bh[ni][0] = *(const uint32_t*)p;
                bh[ni][1] = *(const uint32_t*)(p + 8);
                const __nv_bfloat16* q = p + B_SEC;
                bl[ni][0] = *(const uint32_t*)q;
                bl[ni][1] = *(const uint32_t*)(q + 8);
            }
#pragma unroll
            for (int mi = 0; mi < 2; ++mi)
#pragma unroll
                for (int ni = 0; ni < 4; ++ni) {
                    mma16816(acc[mi][ni], ah[mi], bh[ni]);
                    mma16816(acc[mi][ni], ah[mi], bl[ni]);
                    mma16816(acc[mi][ni], al[mi], bh[ni]);
                }
        }
        __syncthreads();
    }

    // epilogue: direct C writes + per-column stats
#pragma unroll
    for (int ni = 0; ni < 4; ++ni) {
        int colL = wn * 32 + ni * 8 + 2 * t;
        float s0 = 0.f, q0 = 0.f, s1 = 0.f, q1 = 0.f;
#pragma unroll
        for (int mi = 0; mi < 2; ++mi) {
            float* f = acc[mi][ni];
            int row = m0 + wm * 32 + mi * 16 + g;
            if (row < M) {
                C[(size_t)row * Nc + n0 + colL] = f[0];
                C[(size_t)row * Nc + n0 + colL + 1] = f[1];
                s0 += f[0]; q0 += f[0] * f[0];
                s1 += f[1]; q1 += f[1] * f[1];
            }
            if (row + 8 < M) {
                C[(size_t)(row + 8) * Nc + n0 + colL] = f[2];
                C[(size_t)(row + 8) * Nc + n0 + colL + 1] = f[3];
                s0 += f[2]; q0 += f[2] * f[2];
                s1 += f[3]; q1 += f[3] * f[3];
            }
        }
        // reduce over g (lanes differing in bits 2..4)
#pragma unroll
        for (int off = 4; off < 32; off <<= 1) {
            s0 += __shfl_xor_sync(0xffffffffu, s0, off);
            q0 += __shfl_xor_sync(0xffffffffu, q0, off);
            s1 += __shfl_xor_sync(0xffffffffu, s1, off);
            q1 += __shfl_xor_sync(0xffffffffu, q1, off);
        }
        if (g == 0) {
            atomicAdd(&red[colL], s0);
            atomicAdd(&red[64 + colL], q0);
            atomicAdd(&red[colL + 1], s1);
            atomicAdd(&red[64 + colL + 1], q1);
        }
    }
    __syncthreads();
    if (tid < 64) {
        atomicAdd(&g_stats[statOff + n0 + tid], (double)red[tid]);
        atomicAdd(&g_stats[statOff + statC + n0 + tid], (double)red[64 + tid]);
    }
}

// ---------------- final: out = leaky(bn(u2)) + bn(usc), float4 ----------------
__global__ void final_kernel(float4* __restrict__ out, int n4) {
    int i = blockIdx.x * blockDim.x + threadIdx.x;
    if (i >= n4) return;
    int c4 = (i & 63) * 4;
    float4 a = __ldg((const float4*)g_u2 + i);
    float4 s = __ldg((const float4*)g_usc + i);
    float4 o;
#pragma unroll
    for (int j = 0; j < 4; ++j) {
        float2 p2 = __ldg(&g_bnp[128 + c4 + j]);
        float2 ps = __ldg(&g_bnp[384 + c4 + j]);
        float u = fmaf((&a.x)[j], p2.x, p2.y);
        u = (u >= 0.f) ? u : NEG * u;
        (&o.x)[j] = u + fmaf((&s.x)[j], ps.x, ps.y);
    }
    out[i] = o;
}

// ---------------- launch ----------------
extern "C" void kernel_launch(void* const* d_in, const int* in_sizes, int n_in,
                              void* d_out, int out_size) {
    const float* pos    = (const float*)d_in[0];
    const float* x      = (const float*)d_in[1];
    const int*   e_ref  = (const int*)  d_in[2];
    const int*   e_qry  = (const int*)  d_in[3];
    const float* W1     = (const float*)d_in[4];
    const float* g1     = (const float*)d_in[5];
    const float* b1     = (const float*)d_in[6];
    const float* kp     = (const float*)d_in[7];
    const float* Wkp    = (const float*)d_in[8];   // [960,64] row-major
    const float* gkp    = (const float*)d_in[9];
    const float* bkp    = (const float*)d_in[10];
    const float* W2     = (const float*)d_in[11];
    const float* g2     = (const float*)d_in[12];
    const float* b2     = (const float*)d_in[13];
    const float* Wsc    = (const float*)d_in[14];
    const float* gsc    = (const float*)d_in[15];
    const float* bsc    = (const float*)d_in[16];
    float* out = (float*)d_out;

    const int M = NPTS;
    const int E = in_sizes[2];

    float *t_p, *h_p, *u2_p, *usc_p;
    __nv_bfloat16 *xb_p, *yb_p, *Sb_p, *w1b_p, *wkpb_p, *w2b_p, *wscb_p;
    cudaGetSymbolAddress((void**)&t_p,    g_t);
    cudaGetSymbolAddress((void**)&h_p,    g_h);
    cudaGetSymbolAddress((void**)&u2_p,   g_u2);
    cudaGetSymbolAddress((void**)&usc_p,  g_usc);
    cudaGetSymbolAddress((void**)&xb_p,   g_xb);
    cudaGetSymbolAddress((void**)&yb_p,   g_yb);
    cudaGetSymbolAddress((void**)&Sb_p,   g_Sb);
    cudaGetSymbolAddress((void**)&w1b_p,  g_w1b);
    cudaGetSymbolAddress((void**)&wkpb_p, g_wkpb);
    cudaGetSymbolAddress((void**)&w2b_p,  g_w2b);
    cudaGetSymbolAddress((void**)&wscb_p, g_wscb);

    cudaFuncSetAttribute(gemm_mma, cudaFuncAttributeMaxDynamicSharedMemorySize, GSMEM_BYTES);

    // 0. zero counters + stats; bin edges
    zero_kernel<<<(NPTS + 255) / 256, 256>>>();
    scatter_kernel<<<(E + 255) / 256, 256>>>(e_ref, e_qry, E);

    // conversions
    xsplit_kernel<<<(M * DIN + 255) / 256, 256>>>(x, M * DIN);
    wsplit_kernel<<<(DIN * D2 + 255) / 256, 256>>>(W1, w1b_p, DIN, D2);
    wsplit_kernel<<<(KPTS * D2 * D2 + 255) / 256, 256>>>(Wkp, wkpb_p, KPTS * D2, D2);
    wsplit_kernel<<<(D2 * DOUT + 255) / 256, 256>>>(W2, w2b_p, D2, DOUT);
    wsplit_kernel<<<(DIN * DOUT + 255) / 256, 256>>>(Wsc, wscb_p, DIN, DOUT);

    const int MB = (M + 127) / 128;
    int n4_64 = M * D2 / 4;
    int n4_256 = M * DOUT / 4;

    // 1. t = x @ W1   (K=128, Nc=64, stats @0)
    gemm_mma<<<dim3(MB, 1), 256, GSMEM_BYTES>>>(xb_p, w1b_p, t_p, M, DIN, D2, 0, D2);
    // 2. h = leaky(bn(t)) fp32
    bn_prep<<<1, 64>>>(0, D2, g1, b1, 0, M);
    bn_apply64<<<(n4_64 + 255) / 256, 256>>>((const float4*)t_p, (float4*)h_p, 0, n4_64);
    // 3. build split-bf16 S
    sbuild_kernel<<<(M + 7) / 8, 256>>>(pos, kp);
    // 4. y = S @ Wkp  (K=960, Nc=64, stats @128)
    gemm_mma<<<dim3(MB, 1), 256, GSMEM_BYTES>>>(Sb_p, wkpb_p, t_p, M, KPTS * D2, D2, 128, D2);
    // 5. ybn = leaky(bn(y)) -> split bf16
    bn_prep<<<1, 64>>>(128, D2, gkp, bkp, 64, M);
    bn_apply_ysplit<<<(M * D2 + 255) / 256, 256>>>(t_p, 64, M * D2);
    // 6. u2 = ybn @ W2  (K=64, Nc=256, stats @256)
    gemm_mma<<<dim3(MB, 4), 256, GSMEM_BYTES>>>(yb_p, w2b_p, u2_p, M, D2, DOUT, 256, DOUT);
    // 7. usc = x @ Wsc  (K=128, Nc=256, stats @768)
    gemm_mma<<<dim3(MB, 4), 256, GSMEM_BYTES>>>(xb_p, wscb_p, usc_p, M, DIN, DOUT, 768, DOUT);
    // 8. output
    bn_prep<<<1, 256>>>(256, DOUT, g2, b2, 128, M);
    bn_prep<<<1, 256>>>(768, DOUT, gsc, bsc, 384, M);
    final_kernel<<<(n4_256 + 255) / 256, 256>>>((float4*)out, n4_256);
}